// round 16
// baseline (speedup 1.0000x reference)
#include <cuda_runtime.h>
#include <cuda_fp16.h>
#include <math.h>
#include <stdint.h>

#define L6 6
#define BB 32
#define QQ 900
#define DD 256
#define MM (BB*QQ)                 // 28800 tokens per level
#define MD ((size_t)MM*(size_t)DD)

// ---------------- scratch (device globals; allocation-free) ----------------
// transposed weights fp16: [widx][L][N=256][K=256]; widx: 0=cls_w1 1=reg_w1 2=cls_w2 3=reg_w2
__device__ __half g_wb[(size_t)4*L6*DD*DD];

// ---------------- helpers ----------------
__device__ __forceinline__ uint32_t smem_u32(const void* p) {
    uint32_t a;
    asm("{ .reg .u64 t; cvta.to.shared.u64 t, %1; cvt.u32.u64 %0, t; }" : "=r"(a) : "l"(p));
    return a;
}
#define CP_ASYNC16(dst, src) \
    asm volatile("cp.async.cg.shared.global [%0], [%1], 16;" :: "r"(dst), "l"(src))
#define CP_COMMIT() asm volatile("cp.async.commit_group;" ::: "memory")
#define CP_WAIT(n)  asm volatile("cp.async.wait_group %0;" :: "n"(n) : "memory")

#define LDSM4(r, addr) \
    asm volatile("ldmatrix.sync.aligned.m8n8.x4.shared.b16 {%0,%1,%2,%3}, [%4];" \
        : "=r"((r)[0]), "=r"((r)[1]), "=r"((r)[2]), "=r"((r)[3]) : "r"(addr))

__device__ __forceinline__ uint32_t pack2_f16(float x, float y) {
    __half2 h = __halves2half2(__float2half(x), __float2half(y));
    return *reinterpret_cast<uint32_t*>(&h);
}

__device__ __forceinline__ void mma16816(float* c, const uint32_t a[4],
                                         uint32_t b0, uint32_t b1) {
    asm volatile(
        "mma.sync.aligned.m16n8k16.row.col.f32.f16.f16.f32 "
        "{%0,%1,%2,%3}, {%4,%5,%6,%7}, {%8,%9}, {%0,%1,%2,%3};"
        : "+f"(c[0]), "+f"(c[1]), "+f"(c[2]), "+f"(c[3])
        : "r"(a[0]), "r"(a[1]), "r"(a[2]), "r"(a[3]), "r"(b0), "r"(b1));
}

// ---------------- weight transpose + fp16 round ----------------
__global__ void transpose_weights_kernel(const float* __restrict__ w0, const float* __restrict__ w1,
                                         const float* __restrict__ w2, const float* __restrict__ w3)
{
    __shared__ float sT[32][33];
    const float* srcs[4] = {w0, w1, w2, w3};
    const int z = blockIdx.z;
    const int mat = z / L6, l = z - mat * L6;
    const int k0 = blockIdx.y * 32, n0 = blockIdx.x * 32;
    const float* W = srcs[mat] + (size_t)l * DD * DD;   // [K,N] row-major
    sT[threadIdx.y][threadIdx.x] = W[(size_t)(k0 + threadIdx.y) * DD + n0 + threadIdx.x];
    __syncthreads();
    float v = sT[threadIdx.x][threadIdx.y];             // = W[k0+tx][n0+ty]
    size_t o = (((size_t)mat * L6 + l) * DD + (n0 + threadIdx.y)) * DD + k0 + threadIdx.x;
    g_wb[o] = __float2half(v);
}

// ---------------- fused 2-layer HMMA kernel (M=64 tile, 256 thr, 2 CTAs/SM) ----------------
// A converted fp32->fp16 in-kernel into a persistent smem buffer; reused for A2.
// B triple-buffered (prefetch depth 2); A-fragment LDSMs stay inside the loop
// (round-15's hoisted variant caused register spills at the 128-reg cap).
#define LDA 80
#define B_COMP 20480                // 256 rows * 80 B (one B chunk)
#define BUF_BYTES B_COMP
#define LDA2 528                    // A row stride (256 halfs + 8-half pad)

#define OFF_BIAS1  0
#define OFF_GAMMA1 1024
#define OFF_BETA1  2048
#define OFF_BIAS2  3072
#define OFF_GAMMA2 4096
#define OFF_BETA2  5120
#define OFF_S1     6144
#define OFF_S2     7168
#define OFF_W3     8192      // half [256][12] = 6144 -> ends 14336
#define OFF_A      14336     // 64*528 = 33792 -> ends 48128 (A1, later A2)
#define OFF_BUFS   48128     // 3*20480 -> ends 109568
#define SMEM_TOTAL 109568
// psum [4][64][12] (12288 B) aliases OFF_BUFS (buffers dead by final epilogue)

__global__ __launch_bounds__(256, 2)
void fused_mlp_kernel(const float* __restrict__ hs,
                      const float* __restrict__ bc1, const float* __restrict__ gc1,
                      const float* __restrict__ bec1, const float* __restrict__ br1,
                      const float* __restrict__ bc2, const float* __restrict__ gc2,
                      const float* __restrict__ bec2, const float* __restrict__ br2,
                      const float* __restrict__ cw3, const float* __restrict__ cb3,
                      const float* __restrict__ rw3, const float* __restrict__ rb3,
                      const float* __restrict__ init_ref, const float* __restrict__ inter_ref,
                      float* __restrict__ out)
{
    extern __shared__ char smem[];
    float*  bias1S  = (float*)(smem + OFF_BIAS1);
    float*  gamma1S = (float*)(smem + OFF_GAMMA1);
    float*  beta1S  = (float*)(smem + OFF_BETA1);
    float*  bias2S  = (float*)(smem + OFF_BIAS2);
    float*  gamma2S = (float*)(smem + OFF_GAMMA2);
    float*  beta2S  = (float*)(smem + OFF_BETA2);
    float*  s1buf   = (float*)(smem + OFF_S1);
    float*  s2buf   = (float*)(smem + OFF_S2);
    __half* W3s     = (__half*)(smem + OFF_W3);  // [256][12] fp16
    char*   Abuf    = smem + OFF_A;              // A1, then A2
    float*  psum    = (float*)(smem + OFF_BUFS); // aliased over B buffers
    const uint32_t sb = smem_u32(smem);
    const uint32_t bufs_s = sb + OFF_BUFS;

    const int t = threadIdx.x, lane = t & 31, wid = t >> 5;
    const int wm = wid & 1, wn = wid >> 1;       // warp tile: 32 rows x 64 cols
    const int l = blockIdx.z, path = blockIdx.y, m0 = blockIdx.x * 64;

    const __half* W1g = g_wb + ((size_t)(0 * 2 + path) * L6 + l) * DD * DD;
    const __half* W2g = g_wb + ((size_t)(1 * 2 + path) * L6 + l) * DD * DD;
    const float*  Ag  = hs + (size_t)l * MD + (size_t)m0 * DD;   // fp32, [64,256] tile

    // ---- B chunk loader: g in 0..15; g<8: W1 chunk g; g>=8: W2 chunk g-8 ----
    auto load_g = [&](int g) {
        const uint32_t base = bufs_s + (g % 3) * BUF_BYTES;
        const __half* Wsrc = (g < 8) ? W1g : W2g;
        const int kc = (g & 7) * 32;
#pragma unroll
        for (int s = 0; s < 4; ++s) {
            const int idx = s * 256 + t, r = idx >> 2, cc = idx & 3;
            CP_ASYNC16(base + r * LDA + cc * 16, Wsrc + (size_t)r * DD + kc + cc * 8);
        }
    };

    load_g(0); CP_COMMIT();
    load_g(1); CP_COMMIT();

    // ---- A conversion: 64x256 fp32 -> fp16 into Abuf (overlaps chunk-0/1 cp.async) ----
#pragma unroll
    for (int s = 0; s < 16; ++s) {
        const int idx = s * 256 + t;
        const int row = idx >> 6, c4 = idx & 63;        // 64 float4s per row
        const float4 f = *(const float4*)(Ag + (size_t)row * DD + c4 * 4);
        *(uint2*)(Abuf + row * LDA2 + c4 * 8) =
            make_uint2(pack2_f16(f.x, f.y), pack2_f16(f.z, f.w));
    }

    // ---- parameter loads ----
    bias1S[t] = ((path ? br1 : bc1) + l * DD)[t];
    bias2S[t] = ((path ? br2 : bc2) + l * DD)[t];
    if (path == 0) {
        gamma1S[t] = gc1[l * DD + t]; beta1S[t] = bec1[l * DD + t];
        gamma2S[t] = gc2[l * DD + t]; beta2S[t] = bec2[l * DD + t];
    }
    {
        const float* w3g = (path ? rw3 : cw3) + l * 2560;
        for (int idx = t; idx < 2560; idx += 256) {
            const int k = idx / 10, nc = idx - k * 10;
            W3s[k * 12 + nc] = __float2half(w3g[idx]);
        }
    }

    float acc[2][8][4];
#pragma unroll
    for (int mf = 0; mf < 2; ++mf)
#pragma unroll
        for (int nf = 0; nf < 8; ++nf)
#pragma unroll
            for (int i = 0; i < 4; ++i) acc[mf][nf][i] = 0.f;

    const int gr = lane >> 2, gc2v = (lane & 3) << 1;
    const uint32_t b_off = (uint32_t)(wn * 64 + (lane & 7) + ((lane >> 4) & 1) * 8) * LDA
                         + ((lane >> 3) & 1) * 16;
    const uint32_t a_off = sb + OFF_A
                         + (uint32_t)(wm * 32 + (lane & 7) + ((lane >> 3) & 1) * 8) * LDA2
                         + ((lane >> 4) & 1) * 16;

    // ================= mainloop 1 (layer 1; A persistent in smem, B triple-buffered) =================
#pragma unroll 1
    for (int g = 0; g < 8; ++g) {
        CP_WAIT(1);
        __syncthreads();                 // chunk g + A-conv/params visible; g-1 consumed by all
        if (g + 2 <= 9) { load_g(g + 2); CP_COMMIT(); }   // g=6->g8, g=7->g9 (layer-2 chunks)
        const uint32_t baseB = bufs_s + (g % 3) * BUF_BYTES;
#pragma unroll
        for (int ks = 0; ks < 2; ++ks) {
            const uint32_t kb = ks * 32;
            const uint32_t k16off = (uint32_t)(g * 2 + ks) * 32;
            uint32_t ah[2][4];
            LDSM4(ah[0], a_off + k16off);
            LDSM4(ah[1], a_off + 16 * LDA2 + k16off);
#pragma unroll
            for (int np2 = 0; np2 < 2; ++np2) {
                uint32_t bh[2][4];
#pragma unroll
                for (int p = 0; p < 2; ++p)
                    LDSM4(bh[p], baseB + b_off + (np2 * 2 + p) * (16 * LDA) + kb);
                float* a00 = acc[0][4 * np2];
                float* a10 = acc[1][4 * np2];
#pragma unroll
                for (int p = 0; p < 2; ++p) {
                    mma16816(a00 + (2 * p) * 4,     ah[0], bh[p][0], bh[p][1]);
                    mma16816(a10 + (2 * p) * 4,     ah[1], bh[p][0], bh[p][1]);
                    mma16816(a00 + (2 * p + 1) * 4, ah[0], bh[p][2], bh[p][3]);
                    mma16816(a10 + (2 * p + 1) * 4, ah[1], bh[p][2], bh[p][3]);
                }
            }
        }
    }
    __syncthreads();   // all warps done reading A1; safe to overwrite Abuf with A2
    // chunks g=8, g=9 are in flight and land during the epilogue below.

    // ================= inter-layer epilogue: bias1 + (LN1) + ReLU -> Abuf (A2) =================
#pragma unroll
    for (int nf = 0; nf < 8; ++nf) {
        const int cb = wn * 64 + nf * 8 + gc2v;
        const float b0 = bias1S[cb], b1 = bias1S[cb + 1];
#pragma unroll
        for (int mf = 0; mf < 2; ++mf) {
            acc[mf][nf][0] += b0; acc[mf][nf][1] += b1;
            acc[mf][nf][2] += b0; acc[mf][nf][3] += b1;
        }
    }
    float mean_[2][2], rs_[2][2];
    if (path == 0) {
        float s1[2][2] = {{0.f,0.f},{0.f,0.f}}, s2[2][2] = {{0.f,0.f},{0.f,0.f}};
#pragma unroll
        for (int nf = 0; nf < 8; ++nf)
#pragma unroll
            for (int mf = 0; mf < 2; ++mf) {
                s1[mf][0] += acc[mf][nf][0] + acc[mf][nf][1];
                s2[mf][0] += acc[mf][nf][0]*acc[mf][nf][0] + acc[mf][nf][1]*acc[mf][nf][1];
                s1[mf][1] += acc[mf][nf][2] + acc[mf][nf][3];
                s2[mf][1] += acc[mf][nf][2]*acc[mf][nf][2] + acc[mf][nf][3]*acc[mf][nf][3];
            }
#pragma unroll
        for (int mf = 0; mf < 2; ++mf)
#pragma unroll
            for (int h = 0; h < 2; ++h) {
                s1[mf][h] += __shfl_xor_sync(0xffffffffu, s1[mf][h], 1);
                s1[mf][h] += __shfl_xor_sync(0xffffffffu, s1[mf][h], 2);
                s2[mf][h] += __shfl_xor_sync(0xffffffffu, s2[mf][h], 1);
                s2[mf][h] += __shfl_xor_sync(0xffffffffu, s2[mf][h], 2);
            }
        if ((lane & 3) == 0) {
#pragma unroll
            for (int mf = 0; mf < 2; ++mf)
#pragma unroll
                for (int h = 0; h < 2; ++h) {
                    const int row = wm * 32 + mf * 16 + h * 8 + gr;
                    s1buf[wn * 64 + row] = s1[mf][h];
                    s2buf[wn * 64 + row] = s2[mf][h];
                }
        }
        __syncthreads();
#pragma unroll
        for (int mf = 0; mf < 2; ++mf)
#pragma unroll
            for (int h = 0; h < 2; ++h) {
                const int row = wm * 32 + mf * 16 + h * 8 + gr;
                const float t1 = s1buf[row] + s1buf[64 + row] + s1buf[128 + row] + s1buf[192 + row];
                const float t2 = s2buf[row] + s2buf[64 + row] + s2buf[128 + row] + s2buf[192 + row];
                const float mean = t1 * (1.0f / 256.0f);
                const float var  = t2 * (1.0f / 256.0f) - mean * mean;
                mean_[mf][h] = mean;
                rs_[mf][h]   = rsqrtf(var + 1e-5f);
            }
    }
    {
#pragma unroll
        for (int nf = 0; nf < 8; ++nf) {
            const int cb = wn * 64 + nf * 8 + gc2v;
            float g0 = 1.f, g1 = 1.f, be0 = 0.f, be1 = 0.f;
            if (path == 0) { g0 = gamma1S[cb]; g1 = gamma1S[cb + 1]; be0 = beta1S[cb]; be1 = beta1S[cb + 1]; }
#pragma unroll
            for (int mf = 0; mf < 2; ++mf) {
                float y[4];
                if (path == 0) {
                    y[0] = (acc[mf][nf][0] - mean_[mf][0]) * rs_[mf][0] * g0 + be0;
                    y[1] = (acc[mf][nf][1] - mean_[mf][0]) * rs_[mf][0] * g1 + be1;
                    y[2] = (acc[mf][nf][2] - mean_[mf][1]) * rs_[mf][1] * g0 + be0;
                    y[3] = (acc[mf][nf][3] - mean_[mf][1]) * rs_[mf][1] * g1 + be1;
                } else {
                    y[0] = acc[mf][nf][0]; y[1] = acc[mf][nf][1];
                    y[2] = acc[mf][nf][2]; y[3] = acc[mf][nf][3];
                }
#pragma unroll
                for (int i = 0; i < 4; ++i) y[i] = fmaxf(y[i], 0.f);
                const int r0 = wm * 32 + mf * 16 + gr;
                *(uint32_t*)(Abuf + r0 * LDA2 + cb * 2)       = pack2_f16(y[0], y[1]);
                *(uint32_t*)(Abuf + (r0 + 8) * LDA2 + cb * 2) = pack2_f16(y[2], y[3]);
            }
        }
    }
    // zero accumulators for layer 2
#pragma unroll
    for (int mf = 0; mf < 2; ++mf)
#pragma unroll
        for (int nf = 0; nf < 8; ++nf)
#pragma unroll
            for (int i = 0; i < 4; ++i) acc[mf][nf][i] = 0.f;

    // ================= mainloop 2 (layer 2; A2 persistent in smem) =================
#pragma unroll 1
    for (int g = 8; g < 16; ++g) {
        const int kt = g - 8;
        if (g < 15) CP_WAIT(1); else CP_WAIT(0);
        __syncthreads();                 // chunk g + A2 writes visible; g-1 consumed
        if (g + 2 <= 15) { load_g(g + 2); CP_COMMIT(); }
        const uint32_t baseB = bufs_s + (g % 3) * BUF_BYTES;
#pragma unroll
        for (int ks = 0; ks < 2; ++ks) {
            const uint32_t kb = ks * 32;
            const uint32_t k16off = (uint32_t)(kt * 2 + ks) * 32;
            uint32_t ah[2][4];
            LDSM4(ah[0], a_off + k16off);
            LDSM4(ah[1], a_off + 16 * LDA2 + k16off);
#pragma unroll
            for (int np2 = 0; np2 < 2; ++np2) {
                uint32_t bh[2][4];
#pragma unroll
                for (int p = 0; p < 2; ++p)
                    LDSM4(bh[p], baseB + b_off + (np2 * 2 + p) * (16 * LDA) + kb);
                float* a00 = acc[0][4 * np2];
                float* a10 = acc[1][4 * np2];
#pragma unroll
                for (int p = 0; p < 2; ++p) {
                    mma16816(a00 + (2 * p) * 4,     ah[0], bh[p][0], bh[p][1]);
                    mma16816(a10 + (2 * p) * 4,     ah[1], bh[p][0], bh[p][1]);
                    mma16816(a00 + (2 * p + 1) * 4, ah[0], bh[p][2], bh[p][3]);
                    mma16816(a10 + (2 * p + 1) * 4, ah[1], bh[p][2], bh[p][3]);
                }
            }
        }
    }
    __syncthreads();   // buffers dead; psum (aliased) may now be written

    // ================= final epilogue: bias2 + (LN2) + ReLU + head =================
#pragma unroll
    for (int nf = 0; nf < 8; ++nf) {
        const int cb = wn * 64 + nf * 8 + gc2v;
        const float b0 = bias2S[cb], b1 = bias2S[cb + 1];
#pragma unroll
        for (int mf = 0; mf < 2; ++mf) {
            acc[mf][nf][0] += b0; acc[mf][nf][1] += b1;
            acc[mf][nf][2] += b0; acc[mf][nf][3] += b1;
        }
    }
    if (path == 0) {
        float s1[2][2] = {{0.f,0.f},{0.f,0.f}}, s2[2][2] = {{0.f,0.f},{0.f,0.f}};
#pragma unroll
        for (int nf = 0; nf < 8; ++nf)
#pragma unroll
            for (int mf = 0; mf < 2; ++mf) {
                s1[mf][0] += acc[mf][nf][0] + acc[mf][nf][1];
                s2[mf][0] += acc[mf][nf][0]*acc[mf][nf][0] + acc[mf][nf][1]*acc[mf][nf][1];
                s1[mf][1] += acc[mf][nf][2] + acc[mf][nf][3];
                s2[mf][1] += acc[mf][nf][2]*acc[mf][nf][2] + acc[mf][nf][3]*acc[mf][nf][3];
            }
#pragma unroll
        for (int mf = 0; mf < 2; ++mf)
#pragma unroll
            for (int h = 0; h < 2; ++h) {
                s1[mf][h] += __shfl_xor_sync(0xffffffffu, s1[mf][h], 1);
                s1[mf][h] += __shfl_xor_sync(0xffffffffu, s1[mf][h], 2);
                s2[mf][h] += __shfl_xor_sync(0xffffffffu, s2[mf][h], 1);
                s2[mf][h] += __shfl_xor_sync(0xffffffffu, s2[mf][h], 2);
            }
        if ((lane & 3) == 0) {
#pragma unroll
            for (int mf = 0; mf < 2; ++mf)
#pragma unroll
                for (int h = 0; h < 2; ++h) {
                    const int row = wm * 32 + mf * 16 + h * 8 + gr;
                    s1buf[wn * 64 + row] = s1[mf][h];
                    s2buf[wn * 64 + row] = s2[mf][h];
                }
        }
        __syncthreads();
#pragma unroll
        for (int mf = 0; mf < 2; ++mf)
#pragma unroll
            for (int h = 0; h < 2; ++h) {
                const int row = wm * 32 + mf * 16 + h * 8 + gr;
                const float t1 = s1buf[row] + s1buf[64 + row] + s1buf[128 + row] + s1buf[192 + row];
                const float t2 = s2buf[row] + s2buf[64 + row] + s2buf[128 + row] + s2buf[192 + row];
                const float mean = t1 * (1.0f / 256.0f);
                const float var  = t2 * (1.0f / 256.0f) - mean * mean;
                mean_[mf][h] = mean;
                rs_[mf][h]   = rsqrtf(var + 1e-5f);
            }
    }

    // fused head: y -> 10-dim GEMV partials, reduce, coord transform
    float part[4][10];
#pragma unroll
    for (int s = 0; s < 4; ++s)
#pragma unroll
        for (int nc = 0; nc < 10; ++nc) part[s][nc] = 0.f;

#pragma unroll
    for (int nf = 0; nf < 8; ++nf) {
        const int cb = wn * 64 + nf * 8 + gc2v;
        float g0 = 1.f, g1 = 1.f, be0 = 0.f, be1 = 0.f;
        if (path == 0) { g0 = gamma2S[cb]; g1 = gamma2S[cb + 1]; be0 = beta2S[cb]; be1 = beta2S[cb + 1]; }
        float y[2][4];
#pragma unroll
        for (int mf = 0; mf < 2; ++mf) {
            if (path == 0) {
                y[mf][0] = (acc[mf][nf][0] - mean_[mf][0]) * rs_[mf][0] * g0 + be0;
                y[mf][1] = (acc[mf][nf][1] - mean_[mf][0]) * rs_[mf][0] * g1 + be1;
                y[mf][2] = (acc[mf][nf][2] - mean_[mf][1]) * rs_[mf][1] * g0 + be0;
                y[mf][3] = (acc[mf][nf][3] - mean_[mf][1]) * rs_[mf][1] * g1 + be1;
            } else {
                y[mf][0] = acc[mf][nf][0]; y[mf][1] = acc[mf][nf][1];
                y[mf][2] = acc[mf][nf][2]; y[mf][3] = acc[mf][nf][3];
            }
#pragma unroll
            for (int i = 0; i < 4; ++i) y[mf][i] = fmaxf(y[mf][i], 0.f);
        }
        const __half* w0 = &W3s[cb * 12];
        const __half* w1 = &W3s[(cb + 1) * 12];
#pragma unroll
        for (int nc = 0; nc < 10; ++nc) {
            const float a0 = __half2float(w0[nc]), a1 = __half2float(w1[nc]);
#pragma unroll
            for (int mf = 0; mf < 2; ++mf) {
                part[mf * 2 + 0][nc] = fmaf(y[mf][0], a0, fmaf(y[mf][1], a1, part[mf * 2 + 0][nc]));
                part[mf * 2 + 1][nc] = fmaf(y[mf][2], a0, fmaf(y[mf][3], a1, part[mf * 2 + 1][nc]));
            }
        }
    }
#pragma unroll
    for (int s = 0; s < 4; ++s)
#pragma unroll
        for (int nc = 0; nc < 10; ++nc) {
            part[s][nc] += __shfl_xor_sync(0xffffffffu, part[s][nc], 1);
            part[s][nc] += __shfl_xor_sync(0xffffffffu, part[s][nc], 2);
        }
    if ((lane & 3) == 0) {
#pragma unroll
        for (int mf = 0; mf < 2; ++mf)
#pragma unroll
            for (int h = 0; h < 2; ++h) {
                const int row = wm * 32 + mf * 16 + h * 8 + gr;
                float* p = &psum[((size_t)wn * 64 + row) * 12];
#pragma unroll
                for (int nc = 0; nc < 10; ++nc) p[nc] = part[mf * 2 + h][nc];
            }
    }
    __syncthreads();

    if (t < 64) {
        const int row = t;
        const int m = m0 + row;
        const int q = m >> 5, b = m & 31;
        const size_t base = (((size_t)l * BB + b) * QQ + q) * 10;
        float val[10];
        const float* b3 = (path ? rb3 : cb3) + l * 10;
#pragma unroll
        for (int nc = 0; nc < 10; ++nc)
            val[nc] = psum[row * 12 + nc] + psum[(64 + row) * 12 + nc]
                    + psum[(128 + row) * 12 + nc] + psum[(192 + row) * 12 + nc] + b3[nc];
        if (path == 0) {
#pragma unroll
            for (int nc = 0; nc < 10; ++nc) out[base + nc] = val[nc];   // cls scores
        } else {
            const float* rp = (l == 0)
                ? (init_ref + ((size_t)b * QQ + q) * 3)
                : (inter_ref + (((size_t)(l - 1) * BB + b) * QQ + q) * 3);
            float r[3];
#pragma unroll
            for (int i = 0; i < 3; ++i) {
                const float x  = fminf(fmaxf(rp[i], 0.f), 1.f);
                const float x1 = fmaxf(x, 1e-5f);
                const float x2 = fmaxf(1.f - x, 1e-5f);
                r[i] = logf(x1 / x2);
            }
            const float xy0 = 1.f / (1.f + expf(-(val[0] + r[0])));
            const float xy1 = 1.f / (1.f + expf(-(val[1] + r[1])));
            const float z   = 1.f / (1.f + expf(-(val[4] + r[2])));
            float* co = out + (size_t)L6 * BB * QQ * 10 + base;
            co[0] = xy0 * 102.4f - 51.2f;
            co[1] = xy1 * 102.4f - 51.2f;
            co[2] = val[2];
            co[3] = val[3];
            co[4] = z * 8.0f - 5.0f;
            co[5] = val[5]; co[6] = val[6]; co[7] = val[7]; co[8] = val[8]; co[9] = val[9];
        }
    }
}

extern "C" void kernel_launch(void* const* d_in, const int* in_sizes, int n_in,
                              void* d_out, int out_size) {
    const float* hs        = (const float*)d_in[0];
    const float* init_ref  = (const float*)d_in[1];
    const float* inter_ref = (const float*)d_in[2];
    const float* cls_w1    = (const float*)d_in[3];
    const float* cls_b1    = (const float*)d_in[4];
    const float* ln1_g     = (const float*)d_in[5];
    const float* ln1_b     = (const float*)d_in[6];
    const float* cls_w2    = (const float*)d_in[7];
    const float* cls_b2    = (const float*)d_in[8];
    const float* ln2_g     = (const float*)d_in[9];
    const float* ln2_b     = (const float*)d_in[10];
    const float* cls_w3    = (const float*)d_in[11];
    const float* cls_b3    = (const float*)d_in[12];
    const float* reg_w1    = (const float*)d_in[13];
    const float* reg_b1    = (const float*)d_in[14];
    const float* reg_w2    = (const float*)d_in[15];
    const float* reg_b2    = (const float*)d_in[16];
    const float* reg_w3    = (const float*)d_in[17];
    const float* reg_b3    = (const float*)d_in[18];
    float* out = (float*)d_out;

    cudaFuncSetAttribute(fused_mlp_kernel, cudaFuncAttributeMaxDynamicSharedMemorySize, SMEM_TOTAL);

    transpose_weights_kernel<<<dim3(8, 8, 4 * L6), dim3(32, 32)>>>(cls_w1, reg_w1, cls_w2, reg_w2);

    dim3 grid(MM / 64, 2, L6);   // 450 x {cls,reg} x 6
    fused_mlp_kernel<<<grid, 256, SMEM_TOTAL>>>(hs,
                                                cls_b1, ln1_g, ln1_b, reg_b1,
                                                cls_b2, ln2_g, ln2_b, reg_b2,
                                                cls_w3, cls_b3, reg_w3, reg_b3,
                                                init_ref, inter_ref, out);
}

// round 17
// speedup vs baseline: 1.0824x; 1.0824x over previous
#include <cuda_runtime.h>
#include <cuda_fp16.h>
#include <math.h>
#include <stdint.h>

#define L6 6
#define BB 32
#define QQ 900
#define DD 256
#define MM (BB*QQ)                 // 28800 tokens per level
#define MD ((size_t)MM*(size_t)DD)

// ---------------- scratch (device globals; allocation-free) ----------------
// transposed weights fp16: [widx][L][N=256][K=256]; widx: 0=cls_w1 1=reg_w1 2=cls_w2 3=reg_w2
__device__ __half g_wb[(size_t)4*L6*DD*DD];

// ---------------- helpers ----------------
__device__ __forceinline__ uint32_t smem_u32(const void* p) {
    uint32_t a;
    asm("{ .reg .u64 t; cvta.to.shared.u64 t, %1; cvt.u32.u64 %0, t; }" : "=r"(a) : "l"(p));
    return a;
}
#define CP_ASYNC16(dst, src) \
    asm volatile("cp.async.cg.shared.global [%0], [%1], 16;" :: "r"(dst), "l"(src))
#define CP_COMMIT() asm volatile("cp.async.commit_group;" ::: "memory")
#define CP_WAIT(n)  asm volatile("cp.async.wait_group %0;" :: "n"(n) : "memory")

#define LDSM4(r, addr) \
    asm volatile("ldmatrix.sync.aligned.m8n8.x4.shared.b16 {%0,%1,%2,%3}, [%4];" \
        : "=r"((r)[0]), "=r"((r)[1]), "=r"((r)[2]), "=r"((r)[3]) : "r"(addr))

__device__ __forceinline__ uint32_t pack2_f16(float x, float y) {
    __half2 h = __halves2half2(__float2half(x), __float2half(y));
    return *reinterpret_cast<uint32_t*>(&h);
}

__device__ __forceinline__ void mma16816(float* c, const uint32_t a[4],
                                         uint32_t b0, uint32_t b1) {
    asm volatile(
        "mma.sync.aligned.m16n8k16.row.col.f32.f16.f16.f32 "
        "{%0,%1,%2,%3}, {%4,%5,%6,%7}, {%8,%9}, {%0,%1,%2,%3};"
        : "+f"(c[0]), "+f"(c[1]), "+f"(c[2]), "+f"(c[3])
        : "r"(a[0]), "r"(a[1]), "r"(a[2]), "r"(a[3]), "r"(b0), "r"(b1));
}

// ---------------- weight transpose + fp16 round ----------------
__global__ void transpose_weights_kernel(const float* __restrict__ w0, const float* __restrict__ w1,
                                         const float* __restrict__ w2, const float* __restrict__ w3)
{
    __shared__ float sT[32][33];
    const float* srcs[4] = {w0, w1, w2, w3};
    const int z = blockIdx.z;
    const int mat = z / L6, l = z - mat * L6;
    const int k0 = blockIdx.y * 32, n0 = blockIdx.x * 32;
    const float* W = srcs[mat] + (size_t)l * DD * DD;   // [K,N] row-major
    sT[threadIdx.y][threadIdx.x] = W[(size_t)(k0 + threadIdx.y) * DD + n0 + threadIdx.x];
    __syncthreads();
    float v = sT[threadIdx.x][threadIdx.y];             // = W[k0+tx][n0+ty]
    size_t o = (((size_t)mat * L6 + l) * DD + (n0 + threadIdx.y)) * DD + k0 + threadIdx.x;
    g_wb[o] = __float2half(v);
}

// ---------------- fused 2-layer HMMA kernel (M=64 tile, 256 thr, 2 CTAs/SM) ----------------
// A converted fp32->fp16 in-kernel into a persistent smem buffer (no gmem pre-pass).
// The same buffer is reused for the layer-2 activations (A2) after mainloop 1.
// (r14 structure: double-buffered B with (kt&1); mainloops unrolled x2 so buffer
//  bases and A k-offsets are compile-time constants per copy.)
#define LDA 80
#define B_COMP 20480                // 256 rows * 80 B (one B chunk)
#define BUF_BYTES B_COMP
#define LDA2 528                    // A row stride (256 halfs + 8-half pad)

#define OFF_BIAS1  0
#define OFF_GAMMA1 1024
#define OFF_BETA1  2048
#define OFF_BIAS2  3072
#define OFF_GAMMA2 4096
#define OFF_BETA2  5120
#define OFF_S1     6144
#define OFF_S2     7168
#define OFF_W3     8192      // 256*12*4 = 12288 -> ends 20480
#define OFF_A      20480     // 64*528 = 33792 -> ends 54272 (A1, later A2)
#define OFF_BUFS   54272     // 2*20480 -> ends 95232
#define SMEM_TOTAL 95232
// psum [4][64][12] (12288 B) aliases OFF_BUFS (buffers dead by final epilogue)

__global__ __launch_bounds__(256, 2)
void fused_mlp_kernel(const float* __restrict__ hs,
                      const float* __restrict__ bc1, const float* __restrict__ gc1,
                      const float* __restrict__ bec1, const float* __restrict__ br1,
                      const float* __restrict__ bc2, const float* __restrict__ gc2,
                      const float* __restrict__ bec2, const float* __restrict__ br2,
                      const float* __restrict__ cw3, const float* __restrict__ cb3,
                      const float* __restrict__ rw3, const float* __restrict__ rb3,
                      const float* __restrict__ init_ref, const float* __restrict__ inter_ref,
                      float* __restrict__ out)
{
    extern __shared__ char smem[];
    float* bias1S  = (float*)(smem + OFF_BIAS1);
    float* gamma1S = (float*)(smem + OFF_GAMMA1);
    float* beta1S  = (float*)(smem + OFF_BETA1);
    float* bias2S  = (float*)(smem + OFF_BIAS2);
    float* gamma2S = (float*)(smem + OFF_GAMMA2);
    float* beta2S  = (float*)(smem + OFF_BETA2);
    float* s1buf   = (float*)(smem + OFF_S1);
    float* s2buf   = (float*)(smem + OFF_S2);
    float* W3s     = (float*)(smem + OFF_W3);    // [256][12]
    char*  Abuf    = smem + OFF_A;               // A1, then A2
    float* psum    = (float*)(smem + OFF_BUFS);  // aliased over B buffers
    const uint32_t sb = smem_u32(smem);
    const uint32_t bufs_s = sb + OFF_BUFS;

    const int t = threadIdx.x, lane = t & 31, wid = t >> 5;
    const int wm = wid & 1, wn = wid >> 1;       // warp tile: 32 rows x 64 cols
    const int l = blockIdx.z, path = blockIdx.y, m0 = blockIdx.x * 64;

    const __half* W1g = g_wb + ((size_t)(0 * 2 + path) * L6 + l) * DD * DD;
    const __half* W2g = g_wb + ((size_t)(1 * 2 + path) * L6 + l) * DD * DD;
    const float*  Ag  = hs + (size_t)l * MD + (size_t)m0 * DD;   // fp32, [64,256] tile

    // ---- B chunk loader: g in 0..15; g<8: W1 chunk g; g>=8: W2 chunk g-8 ----
    auto load_g = [&](int g, int buf) {
        const uint32_t base = bufs_s + buf * BUF_BYTES;
        const __half* Wsrc = (g < 8) ? W1g : W2g;
        const int kc = (g & 7) * 32;
#pragma unroll
        for (int s = 0; s < 4; ++s) {
            const int idx = s * 256 + t, r = idx >> 2, cc = idx & 3;
            CP_ASYNC16(base + r * LDA + cc * 16, Wsrc + (size_t)r * DD + kc + cc * 8);
        }
    };

    load_g(0, 0); CP_COMMIT();

    // ---- A conversion: 64x256 fp32 -> fp16 into Abuf (overlaps chunk-0 cp.async) ----
#pragma unroll
    for (int s = 0; s < 16; ++s) {
        const int idx = s * 256 + t;
        const int row = idx >> 6, c4 = idx & 63;        // 64 float4s per row
        const float4 f = *(const float4*)(Ag + (size_t)row * DD + c4 * 4);
        *(uint2*)(Abuf + row * LDA2 + c4 * 8) =
            make_uint2(pack2_f16(f.x, f.y), pack2_f16(f.z, f.w));
    }

    // ---- parameter loads ----
    bias1S[t] = ((path ? br1 : bc1) + l * DD)[t];
    bias2S[t] = ((path ? br2 : bc2) + l * DD)[t];
    if (path == 0) {
        gamma1S[t] = gc1[l * DD + t]; beta1S[t] = bec1[l * DD + t];
        gamma2S[t] = gc2[l * DD + t]; beta2S[t] = bec2[l * DD + t];
    }
    {
        const float* w3g = (path ? rw3 : cw3) + l * 2560;
        for (int idx = t; idx < 2560; idx += 256) {
            const int k = idx / 10, nc = idx - k * 10;
            W3s[k * 12 + nc] = w3g[idx];
        }
    }

    float acc[2][8][4];
#pragma unroll
    for (int mf = 0; mf < 2; ++mf)
#pragma unroll
        for (int nf = 0; nf < 8; ++nf)
#pragma unroll
            for (int i = 0; i < 4; ++i) acc[mf][nf][i] = 0.f;

    const int gr = lane >> 2, gc2v = (lane & 3) << 1;
    const uint32_t b_off = (uint32_t)(wn * 64 + (lane & 7) + ((lane >> 4) & 1) * 8) * LDA
                         + ((lane >> 3) & 1) * 16;
    const uint32_t a_off = sb + OFF_A
                         + (uint32_t)(wm * 32 + (lane & 7) + ((lane >> 3) & 1) * 8) * LDA2
                         + ((lane >> 4) & 1) * 16;

    // ================= mainloop 1 (layer 1; A persistent in smem, B double-buffered) =================
    // unroll 2: buffer bases and k-offsets become compile-time constants per copy
#pragma unroll 2
    for (int kt = 0; kt < 8; ++kt) {
        CP_WAIT(0);
        __syncthreads();                 // chunk kt + A conversion visible; kt-1 consumed
        load_g(kt + 1, (kt + 1) & 1);    // kt+1 <= 8 (kt=7 -> W2 chunk 0)
        CP_COMMIT();
        const uint32_t baseB = bufs_s + (kt & 1) * BUF_BYTES;
#pragma unroll
        for (int ks = 0; ks < 2; ++ks) {
            const uint32_t kb = ks * 32;
            const uint32_t k16off = (uint32_t)(kt * 2 + ks) * 32;
            uint32_t ah[2][4];
            LDSM4(ah[0], a_off + k16off);
            LDSM4(ah[1], a_off + 16 * LDA2 + k16off);
#pragma unroll
            for (int np2 = 0; np2 < 2; ++np2) {
                uint32_t bh[2][4];
#pragma unroll
                for (int p = 0; p < 2; ++p)
                    LDSM4(bh[p], baseB + b_off + (np2 * 2 + p) * (16 * LDA) + kb);
                float* a00 = acc[0][4 * np2];
                float* a10 = acc[1][4 * np2];
#pragma unroll
                for (int p = 0; p < 2; ++p) {
                    mma16816(a00 + (2 * p) * 4,     ah[0], bh[p][0], bh[p][1]);
                    mma16816(a10 + (2 * p) * 4,     ah[1], bh[p][0], bh[p][1]);
                    mma16816(a00 + (2 * p + 1) * 4, ah[0], bh[p][2], bh[p][3]);
                    mma16816(a10 + (2 * p + 1) * 4, ah[1], bh[p][2], bh[p][3]);
                }
            }
        }
    }
    __syncthreads();   // all warps done reading A1; safe to overwrite Abuf with A2

    // ================= inter-layer epilogue: bias1 + (LN1) + ReLU -> Abuf (A2) =================
#pragma unroll
    for (int nf = 0; nf < 8; ++nf) {
        const int cb = wn * 64 + nf * 8 + gc2v;
        const float b0 = bias1S[cb], b1 = bias1S[cb + 1];
#pragma unroll
        for (int mf = 0; mf < 2; ++mf) {
            acc[mf][nf][0] += b0; acc[mf][nf][1] += b1;
            acc[mf][nf][2] += b0; acc[mf][nf][3] += b1;
        }
    }
    float mean_[2][2], rs_[2][2];
    if (path == 0) {
        float s1[2][2] = {{0.f,0.f},{0.f,0.f}}, s2[2][2] = {{0.f,0.f},{0.f,0.f}};
#pragma unroll
        for (int nf = 0; nf < 8; ++nf)
#pragma unroll
            for (int mf = 0; mf < 2; ++mf) {
                s1[mf][0] += acc[mf][nf][0] + acc[mf][nf][1];
                s2[mf][0] += acc[mf][nf][0]*acc[mf][nf][0] + acc[mf][nf][1]*acc[mf][nf][1];
                s1[mf][1] += acc[mf][nf][2] + acc[mf][nf][3];
                s2[mf][1] += acc[mf][nf][2]*acc[mf][nf][2] + acc[mf][nf][3]*acc[mf][nf][3];
            }
#pragma unroll
        for (int mf = 0; mf < 2; ++mf)
#pragma unroll
            for (int h = 0; h < 2; ++h) {
                s1[mf][h] += __shfl_xor_sync(0xffffffffu, s1[mf][h], 1);
                s1[mf][h] += __shfl_xor_sync(0xffffffffu, s1[mf][h], 2);
                s2[mf][h] += __shfl_xor_sync(0xffffffffu, s2[mf][h], 1);
                s2[mf][h] += __shfl_xor_sync(0xffffffffu, s2[mf][h], 2);
            }
        if ((lane & 3) == 0) {
#pragma unroll
            for (int mf = 0; mf < 2; ++mf)
#pragma unroll
                for (int h = 0; h < 2; ++h) {
                    const int row = wm * 32 + mf * 16 + h * 8 + gr;
                    s1buf[wn * 64 + row] = s1[mf][h];
                    s2buf[wn * 64 + row] = s2[mf][h];
                }
        }
        __syncthreads();
#pragma unroll
        for (int mf = 0; mf < 2; ++mf)
#pragma unroll
            for (int h = 0; h < 2; ++h) {
                const int row = wm * 32 + mf * 16 + h * 8 + gr;
                const float t1 = s1buf[row] + s1buf[64 + row] + s1buf[128 + row] + s1buf[192 + row];
                const float t2 = s2buf[row] + s2buf[64 + row] + s2buf[128 + row] + s2buf[192 + row];
                const float mean = t1 * (1.0f / 256.0f);
                const float var  = t2 * (1.0f / 256.0f) - mean * mean;
                mean_[mf][h] = mean;
                rs_[mf][h]   = rsqrtf(var + 1e-5f);
            }
    }
    {
#pragma unroll
        for (int nf = 0; nf < 8; ++nf) {
            const int cb = wn * 64 + nf * 8 + gc2v;
            float g0 = 1.f, g1 = 1.f, be0 = 0.f, be1 = 0.f;
            if (path == 0) { g0 = gamma1S[cb]; g1 = gamma1S[cb + 1]; be0 = beta1S[cb]; be1 = beta1S[cb + 1]; }
#pragma unroll
            for (int mf = 0; mf < 2; ++mf) {
                float y[4];
                if (path == 0) {
                    y[0] = (acc[mf][nf][0] - mean_[mf][0]) * rs_[mf][0] * g0 + be0;
                    y[1] = (acc[mf][nf][1] - mean_[mf][0]) * rs_[mf][0] * g1 + be1;
                    y[2] = (acc[mf][nf][2] - mean_[mf][1]) * rs_[mf][1] * g0 + be0;
                    y[3] = (acc[mf][nf][3] - mean_[mf][1]) * rs_[mf][1] * g1 + be1;
                } else {
                    y[0] = acc[mf][nf][0]; y[1] = acc[mf][nf][1];
                    y[2] = acc[mf][nf][2]; y[3] = acc[mf][nf][3];
                }
#pragma unroll
                for (int i = 0; i < 4; ++i) y[i] = fmaxf(y[i], 0.f);
                const int r0 = wm * 32 + mf * 16 + gr;
                *(uint32_t*)(Abuf + r0 * LDA2 + cb * 2)       = pack2_f16(y[0], y[1]);
                *(uint32_t*)(Abuf + (r0 + 8) * LDA2 + cb * 2) = pack2_f16(y[2], y[3]);
            }
        }
    }
    // zero accumulators for layer 2
#pragma unroll
    for (int mf = 0; mf < 2; ++mf)
#pragma unroll
        for (int nf = 0; nf < 8; ++nf)
#pragma unroll
            for (int i = 0; i < 4; ++i) acc[mf][nf][i] = 0.f;

    // ================= mainloop 2 (layer 2; A from smem A2) =================
#pragma unroll 2
    for (int kt = 0; kt < 8; ++kt) {
        const int g = 8 + kt;
        CP_WAIT(0);
        __syncthreads();                 // B2 chunk g visible; A2 writes visible (kt==0)
        if (kt < 7) { load_g(g + 1, (g + 1) & 1); CP_COMMIT(); }
        const uint32_t baseB = bufs_s + (g & 1) * BUF_BYTES;
#pragma unroll
        for (int ks = 0; ks < 2; ++ks) {
            const uint32_t kb = ks * 32;
            const uint32_t k16off = (uint32_t)(kt * 2 + ks) * 32;
            uint32_t ah[2][4];
            LDSM4(ah[0], a_off + k16off);
            LDSM4(ah[1], a_off + 16 * LDA2 + k16off);
#pragma unroll
            for (int np2 = 0; np2 < 2; ++np2) {
                uint32_t bh[2][4];
#pragma unroll
                for (int p = 0; p < 2; ++p)
                    LDSM4(bh[p], baseB + b_off + (np2 * 2 + p) * (16 * LDA) + kb);
                float* a00 = acc[0][4 * np2];
                float* a10 = acc[1][4 * np2];
#pragma unroll
                for (int p = 0; p < 2; ++p) {
                    mma16816(a00 + (2 * p) * 4,     ah[0], bh[p][0], bh[p][1]);
                    mma16816(a10 + (2 * p) * 4,     ah[1], bh[p][0], bh[p][1]);
                    mma16816(a00 + (2 * p + 1) * 4, ah[0], bh[p][2], bh[p][3]);
                    mma16816(a10 + (2 * p + 1) * 4, ah[1], bh[p][2], bh[p][3]);
                }
            }
        }
    }
    __syncthreads();   // buffers dead; psum (aliased) may now be written

    // ================= final epilogue: bias2 + (LN2) + ReLU + head =================
#pragma unroll
    for (int nf = 0; nf < 8; ++nf) {
        const int cb = wn * 64 + nf * 8 + gc2v;
        const float b0 = bias2S[cb], b1 = bias2S[cb + 1];
#pragma unroll
        for (int mf = 0; mf < 2; ++mf) {
            acc[mf][nf][0] += b0; acc[mf][nf][1] += b1;
            acc[mf][nf][2] += b0; acc[mf][nf][3] += b1;
        }
    }
    if (path == 0) {
        float s1[2][2] = {{0.f,0.f},{0.f,0.f}}, s2[2][2] = {{0.f,0.f},{0.f,0.f}};
#pragma unroll
        for (int nf = 0; nf < 8; ++nf)
#pragma unroll
            for (int mf = 0; mf < 2; ++mf) {
                s1[mf][0] += acc[mf][nf][0] + acc[mf][nf][1];
                s2[mf][0] += acc[mf][nf][0]*acc[mf][nf][0] + acc[mf][nf][1]*acc[mf][nf][1];
                s1[mf][1] += acc[mf][nf][2] + acc[mf][nf][3];
                s2[mf][1] += acc[mf][nf][2]*acc[mf][nf][2] + acc[mf][nf][3]*acc[mf][nf][3];
            }
#pragma unroll
        for (int mf = 0; mf < 2; ++mf)
#pragma unroll
            for (int h = 0; h < 2; ++h) {
                s1[mf][h] += __shfl_xor_sync(0xffffffffu, s1[mf][h], 1);
                s1[mf][h] += __shfl_xor_sync(0xffffffffu, s1[mf][h], 2);
                s2[mf][h] += __shfl_xor_sync(0xffffffffu, s2[mf][h], 1);
                s2[mf][h] += __shfl_xor_sync(0xffffffffu, s2[mf][h], 2);
            }
        if ((lane & 3) == 0) {
#pragma unroll
            for (int mf = 0; mf < 2; ++mf)
#pragma unroll
                for (int h = 0; h < 2; ++h) {
                    const int row = wm * 32 + mf * 16 + h * 8 + gr;
                    s1buf[wn * 64 + row] = s1[mf][h];
                    s2buf[wn * 64 + row] = s2[mf][h];
                }
        }
        __syncthreads();
#pragma unroll
        for (int mf = 0; mf < 2; ++mf)
#pragma unroll
            for (int h = 0; h < 2; ++h) {
                const int row = wm * 32 + mf * 16 + h * 8 + gr;
                const float t1 = s1buf[row] + s1buf[64 + row] + s1buf[128 + row] + s1buf[192 + row];
                const float t2 = s2buf[row] + s2buf[64 + row] + s2buf[128 + row] + s2buf[192 + row];
                const float mean = t1 * (1.0f / 256.0f);
                const float var  = t2 * (1.0f / 256.0f) - mean * mean;
                mean_[mf][h] = mean;
                rs_[mf][h]   = rsqrtf(var + 1e-5f);
            }
    }

    // fused head: y -> 10-dim GEMV partials, reduce, coord transform
    float part[4][10];
#pragma unroll
    for (int s = 0; s < 4; ++s)
#pragma unroll
        for (int nc = 0; nc < 10; ++nc) part[s][nc] = 0.f;

#pragma unroll
    for (int nf = 0; nf < 8; ++nf) {
        const int cb = wn * 64 + nf * 8 + gc2v;
        float g0 = 1.f, g1 = 1.f, be0 = 0.f, be1 = 0.f;
        if (path == 0) { g0 = gamma2S[cb]; g1 = gamma2S[cb + 1]; be0 = beta2S[cb]; be1 = beta2S[cb + 1]; }
        float y[2][4];
#pragma unroll
        for (int mf = 0; mf < 2; ++mf) {
            if (path == 0) {
                y[mf][0] = (acc[mf][nf][0] - mean_[mf][0]) * rs_[mf][0] * g0 + be0;
                y[mf][1] = (acc[mf][nf][1] - mean_[mf][0]) * rs_[mf][0] * g1 + be1;
                y[mf][2] = (acc[mf][nf][2] - mean_[mf][1]) * rs_[mf][1] * g0 + be0;
                y[mf][3] = (acc[mf][nf][3] - mean_[mf][1]) * rs_[mf][1] * g1 + be1;
            } else {
                y[mf][0] = acc[mf][nf][0]; y[mf][1] = acc[mf][nf][1];
                y[mf][2] = acc[mf][nf][2]; y[mf][3] = acc[mf][nf][3];
            }
#pragma unroll
            for (int i = 0; i < 4; ++i) y[mf][i] = fmaxf(y[mf][i], 0.f);
        }
        const float* w0 = &W3s[cb * 12];
        const float* w1 = &W3s[(cb + 1) * 12];
#pragma unroll
        for (int nc = 0; nc < 10; ++nc) {
            const float a0 = w0[nc], a1 = w1[nc];
#pragma unroll
            for (int mf = 0; mf < 2; ++mf) {
                part[mf * 2 + 0][nc] = fmaf(y[mf][0], a0, fmaf(y[mf][1], a1, part[mf * 2 + 0][nc]));
                part[mf * 2 + 1][nc] = fmaf(y[mf][2], a0, fmaf(y[mf][3], a1, part[mf * 2 + 1][nc]));
            }
        }
    }
#pragma unroll
    for (int s = 0; s < 4; ++s)
#pragma unroll
        for (int nc = 0; nc < 10; ++nc) {
            part[s][nc] += __shfl_xor_sync(0xffffffffu, part[s][nc], 1);
            part[s][nc] += __shfl_xor_sync(0xffffffffu, part[s][nc], 2);
        }
    if ((lane & 3) == 0) {
#pragma unroll
        for (int mf = 0; mf < 2; ++mf)
#pragma unroll
            for (int h = 0; h < 2; ++h) {
                const int row = wm * 32 + mf * 16 + h * 8 + gr;
                float* p = &psum[((size_t)wn * 64 + row) * 12];
#pragma unroll
                for (int nc = 0; nc < 10; ++nc) p[nc] = part[mf * 2 + h][nc];
            }
    }
    __syncthreads();

    if (t < 64) {
        const int row = t;
        const int m = m0 + row;
        const int q = m >> 5, b = m & 31;
        const size_t base = (((size_t)l * BB + b) * QQ + q) * 10;
        float val[10];
        const float* b3 = (path ? rb3 : cb3) + l * 10;
#pragma unroll
        for (int nc = 0; nc < 10; ++nc)
            val[nc] = psum[row * 12 + nc] + psum[(64 + row) * 12 + nc]
                    + psum[(128 + row) * 12 + nc] + psum[(192 + row) * 12 + nc] + b3[nc];
        if (path == 0) {
#pragma unroll
            for (int nc = 0; nc < 10; ++nc) out[base + nc] = val[nc];   // cls scores
        } else {
            const float* rp = (l == 0)
                ? (init_ref + ((size_t)b * QQ + q) * 3)
                : (inter_ref + (((size_t)(l - 1) * BB + b) * QQ + q) * 3);
            float r[3];
#pragma unroll
            for (int i = 0; i < 3; ++i) {
                const float x  = fminf(fmaxf(rp[i], 0.f), 1.f);
                const float x1 = fmaxf(x, 1e-5f);
                const float x2 = fmaxf(1.f - x, 1e-5f);
                r[i] = logf(x1 / x2);
            }
            const float xy0 = 1.f / (1.f + expf(-(val[0] + r[0])));
            const float xy1 = 1.f / (1.f + expf(-(val[1] + r[1])));
            const float z   = 1.f / (1.f + expf(-(val[4] + r[2])));
            float* co = out + (size_t)L6 * BB * QQ * 10 + base;
            co[0] = xy0 * 102.4f - 51.2f;
            co[1] = xy1 * 102.4f - 51.2f;
            co[2] = val[2];
            co[3] = val[3];
            co[4] = z * 8.0f - 5.0f;
            co[5] = val[5]; co[6] = val[6]; co[7] = val[7]; co[8] = val[8]; co[9] = val[9];
        }
    }
}

extern "C" void kernel_launch(void* const* d_in, const int* in_sizes, int n_in,
                              void* d_out, int out_size) {
    const float* hs        = (const float*)d_in[0];
    const float* init_ref  = (const float*)d_in[1];
    const float* inter_ref = (const float*)d_in[2];
    const float* cls_w1    = (const float*)d_in[3];
    const float* cls_b1    = (const float*)d_in[4];
    const float* ln1_g     = (const float*)d_in[5];
    const float* ln1_b     = (const float*)d_in[6];
    const float* cls_w2    = (const float*)d_in[7];
    const float* cls_b2    = (const float*)d_in[8];
    const float* ln2_g     = (const float*)d_in[9];
    const float* ln2_b     = (const float*)d_in[10];
    const float* cls_w3    = (const float*)d_in[11];
    const float* cls_b3    = (const float*)d_in[12];
    const float* reg_w1    = (const float*)d_in[13];
    const float* reg_b1    = (const float*)d_in[14];
    const float* reg_w2    = (const float*)d_in[15];
    const float* reg_b2    = (const float*)d_in[16];
    const float* reg_w3    = (const float*)d_in[17];
    const float* reg_b3    = (const float*)d_in[18];
    float* out = (float*)d_out;

    cudaFuncSetAttribute(fused_mlp_kernel, cudaFuncAttributeMaxDynamicSharedMemorySize, SMEM_TOTAL);

    transpose_weights_kernel<<<dim3(8, 8, 4 * L6), dim3(32, 32)>>>(cls_w1, reg_w1, cls_w2, reg_w2);

    dim3 grid(MM / 64, 2, L6);   // 450 x {cls,reg} x 6
    fused_mlp_kernel<<<grid, 256, SMEM_TOTAL>>>(hs,
                                                cls_b1, ln1_g, ln1_b, reg_b1,
                                                cls_b2, ln2_g, ln2_b, reg_b2,
                                                cls_w3, cls_b3, reg_w3, reg_b3,
                                                init_ref, inter_ref, out);
}